// round 7
// baseline (speedup 1.0000x reference)
#include <cuda_runtime.h>
#include <cuda_bf16.h>
#include <cstdint>

#define HD   256          // hidden dim
#define BB   256          // batch
#define TT   512          // seq len
#define NP   (BB/2)       // batch pairs = 128
#define NB   128          // persistent grid size (1 CTA/SM, co-resident)
#define NT   256          // threads per CTA

// ---------------------------------------------------------------------------
// Global state (allocation-free scratch)
// Packed-pair layout: [k][pair] float2  (pair p = batches 2p, 2p+1)
// ---------------------------------------------------------------------------
__device__ float2 g_hpk[3][2][HD][NP];      // ping-pong h per layer, 3MB
__device__ float2 g_x[TT][NP];              // transposed packed input, 512KB
__device__ float2 g_hist[TT][HD][NP];       // h3 history, 134MB
__device__ int               g_bar_count;
__device__ volatile unsigned g_bar_gen;

// ---------------------------------------------------------------------------
// Packed f32x2 (Blackwell FFMA2 via PTX only)
// ---------------------------------------------------------------------------
#define FMA2(acc, a, b) asm("fma.rn.f32x2 %0, %1, %2, %0;" : "+l"(acc) : "l"(a), "l"(b))
__device__ __forceinline__ unsigned long long splat2(float w) {
    unsigned long long r; asm("mov.b64 %0, {%1, %1};" : "=l"(r) : "f"(w)); return r;
}
__device__ __forceinline__ float2 unpack2(unsigned long long v) {
    float2 r; asm("mov.b64 {%0, %1}, %2;" : "=f"(r.x), "=f"(r.y) : "l"(v)); return r;
}
__device__ __forceinline__ float sigf(float x) { return 1.f / (1.f + __expf(-x)); }

// ---------------------------------------------------------------------------
// SMEM layout (~192.5 KB dynamic)
// ---------------------------------------------------------------------------
struct Smem {
    float  w[5][HD * 32];        // 5 weight slices [k][32 rows], 160KB
    float2 act[2][64 * 32];      // double-buffered act chunk [k_local][32 pairs], 32KB
    float  w1ih[32];             // layer-1 input column
    float  bias[3][32];          // fused b_ih + b_hh per row
};
#define SMEM_BYTES (sizeof(Smem))

// ---------------------------------------------------------------------------
// Grid barrier (sense via monotonically increasing generation)
// ---------------------------------------------------------------------------
__device__ __forceinline__ void grid_sync(unsigned target) {
    __syncthreads();
    if (threadIdx.x == 0) {
        __threadfence();
        if (atomicAdd(&g_bar_count, 1) == NB - 1) {
            g_bar_count = 0;
            __threadfence();
            g_bar_gen = target;
        } else {
            while (g_bar_gen < target) { }
            __threadfence();
        }
    }
    __syncthreads();
}

// ---------------------------------------------------------------------------
// acc[p] += sum_k W[k][r] * act_pair[k][gp + pg*4 + p],  k = 0..255
// 4 chunks of 64 k, double-buffered SMEM staging with LDG.cg prefetch.
// Warp = 32 rows (lane r), all lanes share pair-group pg.
// ---------------------------------------------------------------------------
__device__ __forceinline__ void accum_mat(
    unsigned long long acc[4],
    const float2* __restrict__ gact,   // [256][128] activation slice base
    const float*  __restrict__ sw,     // [256][32] weight slice
    float2* sbuf,                      // [2][64*32]
    int gp, int r, int pg, int tid)
{
    const int kl = tid >> 2;          // 0..63 : k within chunk
    const int q  = tid & 3;           // quarter of the 32-pair row

    // stage chunk 0
    {
        const float4* s0 = (const float4*)(gact + (size_t)kl * NP + gp) + q * 4;
        float4 p0 = __ldcg(s0 + 0), p1 = __ldcg(s0 + 1),
               p2 = __ldcg(s0 + 2), p3 = __ldcg(s0 + 3);
        float4* d0 = (float4*)(sbuf + (size_t)kl * 32) + q * 4;
        d0[0] = p0; d0[1] = p1; d0[2] = p2; d0[3] = p3;
    }
    __syncthreads();

    #pragma unroll
    for (int c = 0; c < 4; c++) {
        float4 n0, n1, n2, n3;
        if (c < 3) {
            const float4* sn = (const float4*)(gact + ((size_t)(c + 1) * 64 + kl) * NP + gp) + q * 4;
            n0 = __ldcg(sn + 0); n1 = __ldcg(sn + 1);
            n2 = __ldcg(sn + 2); n3 = __ldcg(sn + 3);
        }
        const float2* ab = sbuf + (size_t)(c & 1) * (64 * 32);
        const float*  wk = sw + c * 64 * 32;
        #pragma unroll 8
        for (int k = 0; k < 64; k++) {
            unsigned long long ws = splat2(wk[k * 32 + r]);
            const ulonglong2* ap = (const ulonglong2*)(ab + k * 32 + pg * 4);
            ulonglong2 u0 = ap[0], u1 = ap[1];
            FMA2(acc[0], ws, u0.x);
            FMA2(acc[1], ws, u0.y);
            FMA2(acc[2], ws, u1.x);
            FMA2(acc[3], ws, u1.y);
        }
        if (c < 3) {
            float4* dn = (float4*)(sbuf + (size_t)((c + 1) & 1) * (64 * 32) + (size_t)kl * 32) + q * 4;
            dn[0] = n0; dn[1] = n1; dn[2] = n2; dn[3] = n3;
            __syncthreads();
        }
    }
}

// ---------------------------------------------------------------------------
// LSTM pointwise: gather 4 gates via warp shuffle (row r = g*8+jj), update
// register-resident c, write h pairs to global (and optionally hist).
// ---------------------------------------------------------------------------
__device__ __forceinline__ void pointwise(
    unsigned long long acc[4], float2 cst[4],
    const float* sbias, float2* hdst, float2* histdst,
    int r, int pg, int gp, int ut)
{
    const int jj = r & 7;
    unsigned long long af[4], ag[4], ao[4];
    #pragma unroll
    for (int p = 0; p < 4; p++) {
        af[p] = __shfl_sync(0xFFFFFFFFu, acc[p], jj + 8);
        ag[p] = __shfl_sync(0xFFFFFFFFu, acc[p], jj + 16);
        ao[p] = __shfl_sync(0xFFFFFFFFu, acc[p], jj + 24);
    }
    if (r < 8) {
        const float bi = sbias[r], bf = sbias[8 + r], bg = sbias[16 + r], bo = sbias[24 + r];
        float2 h[4];
        #pragma unroll
        for (int p = 0; p < 4; p++) {
            float2 vi = unpack2(acc[p]), vf = unpack2(af[p]);
            float2 vg = unpack2(ag[p]), vo = unpack2(ao[p]);
            {   // batch 2p
                float I = sigf(vi.x + bi), F = sigf(vf.x + bf);
                float G = tanhf(vg.x + bg), O = sigf(vo.x + bo);
                float cn = F * cst[p].x + I * G;
                cst[p].x = cn; h[p].x = O * tanhf(cn);
            }
            {   // batch 2p+1
                float I = sigf(vi.y + bi), F = sigf(vf.y + bf);
                float G = tanhf(vg.y + bg), O = sigf(vo.y + bo);
                float cn = F * cst[p].y + I * G;
                cst[p].y = cn; h[p].y = O * tanhf(cn);
            }
        }
        float2* d = hdst + (size_t)(ut * 8 + r) * NP + gp + pg * 4;
        ((float4*)d)[0] = make_float4(h[0].x, h[0].y, h[1].x, h[1].y);
        ((float4*)d)[1] = make_float4(h[2].x, h[2].y, h[3].x, h[3].y);
        if (histdst) {
            float2* hd = histdst + (size_t)(ut * 8 + r) * NP + gp + pg * 4;
            ((float4*)hd)[0] = make_float4(h[0].x, h[0].y, h[1].x, h[1].y);
            ((float4*)hd)[1] = make_float4(h[2].x, h[2].y, h[3].x, h[3].y);
        }
    }
}

// ---------------------------------------------------------------------------
// Persistent kernel: 128 CTAs = 4 batch-tiles x 32 unit-tiles.
// Super-step s: L1@t=s, L2@t=s-1, L3@t=s-2, then grid barrier.
// ---------------------------------------------------------------------------
__global__ void __launch_bounds__(NT, 1)
lstm_persistent(const float* __restrict__ W_ih1, const float* __restrict__ W_hh1,
                const float* __restrict__ b_ih1, const float* __restrict__ b_hh1,
                const float* __restrict__ W_ih2, const float* __restrict__ W_hh2,
                const float* __restrict__ b_ih2, const float* __restrict__ b_hh2,
                const float* __restrict__ W_ih3, const float* __restrict__ W_hh3,
                const float* __restrict__ b_ih3, const float* __restrict__ b_hh3)
{
    extern __shared__ __align__(16) unsigned char smem_raw[];
    Smem* sm = (Smem*)smem_raw;

    const int tid = threadIdx.x;
    const int r   = tid & 31;              // row lane: gate g = r>>3, unit jj = r&7
    const int pg  = tid >> 5;              // pair group 0..7 (4 pairs each)
    const int bt  = blockIdx.x & 3;        // batch tile
    const int ut  = blockIdx.x >> 2;       // unit tile (8 hidden units)
    const int gp  = bt * 32;               // global pair base
    const int grow = ((r >> 3) << 8) + (ut << 3) + (r & 7);  // global gate row

    // ---- stage weights (once, reused 512 steps) ----
    const float* wsrc[5] = { W_hh1, W_ih2, W_hh2, W_ih3, W_hh3 };
    #pragma unroll
    for (int m = 0; m < 5; m++) {
        const float* src = wsrc[m] + (size_t)grow * HD;
        for (int k = tid >> 5; k < HD; k += 8)
            sm->w[m][k * 32 + r] = src[k];
    }
    if (tid < 32) {
        sm->w1ih[r]    = W_ih1[grow];
        sm->bias[0][r] = b_ih1[grow] + b_hh1[grow];
        sm->bias[1][r] = b_ih2[grow] + b_hh2[grow];
        sm->bias[2][r] = b_ih3[grow] + b_hh3[grow];
    }
    __syncthreads();

    // register-resident cell state
    float2 c1[4], c2[4], c3[4];
    #pragma unroll
    for (int p = 0; p < 4; p++) {
        c1[p] = make_float2(0.f, 0.f);
        c2[p] = make_float2(0.f, 0.f);
        c3[p] = make_float2(0.f, 0.f);
    }

    for (int s = 0; s < TT + 2; s++) {
        const int rp = (s + 1) & 1;        // read parity ( = (s-1)&1 )
        const int wp = s & 1;              // write parity

        // ---- layer 1 @ t = s ----
        if (s < TT) {
            unsigned long long acc[4] = {0ull, 0ull, 0ull, 0ull};
            unsigned long long ws1 = splat2(sm->w1ih[r]);
            const ulonglong2* xp = (const ulonglong2*)(&g_x[s][gp + pg * 4]);
            ulonglong2 x0 = xp[0], x1 = xp[1];
            FMA2(acc[0], ws1, x0.x); FMA2(acc[1], ws1, x0.y);
            FMA2(acc[2], ws1, x1.x); FMA2(acc[3], ws1, x1.y);
            accum_mat(acc, &g_hpk[0][rp][0][0], sm->w[0], &sm->act[0][0], gp, r, pg, tid);
            pointwise(acc, c1, sm->bias[0], &g_hpk[0][wp][0][0], nullptr, r, pg, gp, ut);
        }
        // ---- layer 2 @ t = s-1 ----
        if (s >= 1 && s <= TT) {
            unsigned long long acc[4] = {0ull, 0ull, 0ull, 0ull};
            accum_mat(acc, &g_hpk[0][rp][0][0], sm->w[1], &sm->act[0][0], gp, r, pg, tid);
            accum_mat(acc, &g_hpk[1][rp][0][0], sm->w[2], &sm->act[0][0], gp, r, pg, tid);
            pointwise(acc, c2, sm->bias[1], &g_hpk[1][wp][0][0], nullptr, r, pg, gp, ut);
        }
        // ---- layer 3 @ t = s-2 (also record hist) ----
        if (s >= 2) {
            unsigned long long acc[4] = {0ull, 0ull, 0ull, 0ull};
            accum_mat(acc, &g_hpk[1][rp][0][0], sm->w[3], &sm->act[0][0], gp, r, pg, tid);
            accum_mat(acc, &g_hpk[2][rp][0][0], sm->w[4], &sm->act[0][0], gp, r, pg, tid);
            pointwise(acc, c3, sm->bias[2], &g_hpk[2][wp][0][0], &g_hist[s - 2][0][0],
                      r, pg, gp, ut);
        }
        grid_sync((unsigned)(s + 1));
    }
}

// ---------------------------------------------------------------------------
// Init: zero h buffers, reset barrier, build packed-transposed input
// ---------------------------------------------------------------------------
__global__ void init_state(const float* __restrict__ input)
{
    const int idx = blockIdx.x * blockDim.x + threadIdx.x;
    const int stride = gridDim.x * blockDim.x;
    if (idx == 0) { g_bar_count = 0; g_bar_gen = 0; }
    float2* hz = &g_hpk[0][0][0][0];
    for (int i = idx; i < 3 * 2 * HD * NP; i += stride)
        hz[i] = make_float2(0.f, 0.f);
    for (int i = idx; i < TT * NP; i += stride) {
        int t = i >> 7, p = i & (NP - 1);
        ((float2*)g_x)[i] = make_float2(input[(size_t)(2 * p) * TT + t],
                                        input[(size_t)(2 * p + 1) * TT + t]);
    }
}

// ---------------------------------------------------------------------------
// Output head: out[b,t] = dot(h3[t,b,:], W_lin) + b_lin
// block = t, thread = b; hist float layout [t][k][b] is coalesced over b.
// ---------------------------------------------------------------------------
__global__ void __launch_bounds__(256)
linear_head(const float* __restrict__ W_lin, const float* __restrict__ b_lin,
            float* __restrict__ out)
{
    __shared__ float sw[HD];
    const int t = blockIdx.x, b = threadIdx.x;
    sw[b] = W_lin[b];
    __syncthreads();
    const float* hp = (const float*)&g_hist[t][0][0];
    float s = 0.f;
    #pragma unroll 8
    for (int k = 0; k < HD; k++)
        s += hp[(size_t)k * BB + b] * sw[k];
    out[(size_t)b * TT + t] = s + b_lin[0];
}

// ---------------------------------------------------------------------------
// 3 graph nodes total: init -> persistent -> head
// ---------------------------------------------------------------------------
extern "C" void kernel_launch(void* const* d_in, const int* in_sizes, int n_in,
                              void* d_out, int out_size)
{
    const float* input = (const float*)d_in[0];
    const float* W_ih1 = (const float*)d_in[1];
    const float* W_hh1 = (const float*)d_in[2];
    const float* b_ih1 = (const float*)d_in[3];
    const float* b_hh1 = (const float*)d_in[4];
    const float* W_ih2 = (const float*)d_in[5];
    const float* W_hh2 = (const float*)d_in[6];
    const float* b_ih2 = (const float*)d_in[7];
    const float* b_hh2 = (const float*)d_in[8];
    const float* W_ih3 = (const float*)d_in[9];
    const float* W_hh3 = (const float*)d_in[10];
    const float* b_ih3 = (const float*)d_in[11];
    const float* b_hh3 = (const float*)d_in[12];
    const float* W_lin = (const float*)d_in[13];
    const float* b_lin = (const float*)d_in[14];
    float* out = (float*)d_out;

    cudaFuncSetAttribute(lstm_persistent,
                         cudaFuncAttributeMaxDynamicSharedMemorySize, (int)SMEM_BYTES);

    init_state<<<256, 256>>>(input);
    lstm_persistent<<<NB, NT, SMEM_BYTES>>>(W_ih1, W_hh1, b_ih1, b_hh1,
                                            W_ih2, W_hh2, b_ih2, b_hh2,
                                            W_ih3, W_hh3, b_ih3, b_hh3);
    linear_head<<<TT, 256>>>(W_lin, b_lin, out);
}

// round 8
// speedup vs baseline: 1.0539x; 1.0539x over previous
#include <cuda_runtime.h>
#include <cuda_bf16.h>
#include <cstdint>

#define HD   256          // hidden dim
#define BB   256          // batch
#define TT   512          // seq len
#define NP   (BB/2)       // batch pairs = 128
#define NB   128          // persistent grid size (1 CTA/SM, co-resident)
#define NT   256          // threads per CTA

// ---------------------------------------------------------------------------
// Global state (allocation-free scratch)
// Packed-pair layout: [k][pair] float2  (pair p = batches 2p, 2p+1)
// ---------------------------------------------------------------------------
__device__ float2 g_hpk[3][2][HD][NP];      // ping-pong h per layer, 3MB
__device__ float2 g_x[TT][NP];              // transposed packed input, 512KB
__device__ float2 g_hist[TT][HD][NP];       // h3 history, 134MB
__device__ int               g_bar_count;
__device__ volatile unsigned g_bar_gen;

// ---------------------------------------------------------------------------
// Packed f32x2 (Blackwell FFMA2 via PTX only)
// ---------------------------------------------------------------------------
#define FMA2(acc, a, b) asm("fma.rn.f32x2 %0, %1, %2, %0;" : "+l"(acc) : "l"(a), "l"(b))
__device__ __forceinline__ unsigned long long splat2(float w) {
    unsigned long long r; asm("mov.b64 %0, {%1, %1};" : "=l"(r) : "f"(w)); return r;
}
__device__ __forceinline__ float2 unpack2(unsigned long long v) {
    float2 r; asm("mov.b64 {%0, %1}, %2;" : "=f"(r.x), "=f"(r.y) : "l"(v)); return r;
}
__device__ __forceinline__ float sigf(float x) { return 1.f / (1.f + __expf(-x)); }

// ---------------------------------------------------------------------------
// SMEM layout (~192.5 KB dynamic)
// ---------------------------------------------------------------------------
struct Smem {
    float  w[5][HD * 32];        // 5 weight slices [k][32 rows], 160KB
    float2 act[2][64 * 32];      // double-buffered act chunk [k_local][32 pairs], 32KB
    float  w1ih[32];             // layer-1 input column
    float  bias[3][32];          // fused b_ih + b_hh per row
};
#define SMEM_BYTES (sizeof(Smem))

// ---------------------------------------------------------------------------
// Grid barrier (sense via monotonically increasing generation)
// ---------------------------------------------------------------------------
__device__ __forceinline__ void grid_sync(unsigned target) {
    __syncthreads();
    if (threadIdx.x == 0) {
        __threadfence();
        if (atomicAdd(&g_bar_count, 1) == NB - 1) {
            g_bar_count = 0;
            __threadfence();
            g_bar_gen = target;
        } else {
            while (g_bar_gen < target) { }
            __threadfence();
        }
    }
    __syncthreads();
}

// ---------------------------------------------------------------------------
// acc[p] += sum_k W[k][r] * act_pair[k][gp + pg*4 + p],  k = 0..255
// 4 chunks of 64 k, double-buffered SMEM staging with LDG.cg prefetch.
// Warp = 32 rows (lane r), all lanes share pair-group pg.
// ---------------------------------------------------------------------------
__device__ __forceinline__ void accum_mat(
    unsigned long long acc[4],
    const float2* __restrict__ gact,   // [256][128] activation slice base
    const float*  __restrict__ sw,     // [256][32] weight slice
    float2* sbuf,                      // [2][64*32]
    int gp, int r, int pg, int tid)
{
    const int kl = tid >> 2;          // 0..63 : k within chunk
    const int q  = tid & 3;           // quarter of the 32-pair row

    // stage chunk 0
    {
        const float4* s0 = (const float4*)(gact + (size_t)kl * NP + gp) + q * 4;
        float4 p0 = __ldcg(s0 + 0), p1 = __ldcg(s0 + 1),
               p2 = __ldcg(s0 + 2), p3 = __ldcg(s0 + 3);
        float4* d0 = (float4*)(sbuf + (size_t)kl * 32) + q * 4;
        d0[0] = p0; d0[1] = p1; d0[2] = p2; d0[3] = p3;
    }
    __syncthreads();

    #pragma unroll
    for (int c = 0; c < 4; c++) {
        float4 n0, n1, n2, n3;
        if (c < 3) {
            const float4* sn = (const float4*)(gact + ((size_t)(c + 1) * 64 + kl) * NP + gp) + q * 4;
            n0 = __ldcg(sn + 0); n1 = __ldcg(sn + 1);
            n2 = __ldcg(sn + 2); n3 = __ldcg(sn + 3);
        }
        const float2* ab = sbuf + (size_t)(c & 1) * (64 * 32);
        const float*  wk = sw + c * 64 * 32;
        #pragma unroll 8
        for (int k = 0; k < 64; k++) {
            unsigned long long ws = splat2(wk[k * 32 + r]);
            const ulonglong2* ap = (const ulonglong2*)(ab + k * 32 + pg * 4);
            ulonglong2 u0 = ap[0], u1 = ap[1];
            FMA2(acc[0], ws, u0.x);
            FMA2(acc[1], ws, u0.y);
            FMA2(acc[2], ws, u1.x);
            FMA2(acc[3], ws, u1.y);
        }
        if (c < 3) {
            float4* dn = (float4*)(sbuf + (size_t)((c + 1) & 1) * (64 * 32) + (size_t)kl * 32) + q * 4;
            dn[0] = n0; dn[1] = n1; dn[2] = n2; dn[3] = n3;
            __syncthreads();
        }
    }
}

// ---------------------------------------------------------------------------
// LSTM pointwise: gather 4 gates via warp shuffle (row r = g*8+jj), update
// register-resident c, write h pairs to global (and optionally hist).
// ---------------------------------------------------------------------------
__device__ __forceinline__ void pointwise(
    unsigned long long acc[4], float2 cst[4],
    const float* sbias, float2* hdst, float2* histdst,
    int r, int pg, int gp, int ut)
{
    const int jj = r & 7;
    unsigned long long af[4], ag[4], ao[4];
    #pragma unroll
    for (int p = 0; p < 4; p++) {
        af[p] = __shfl_sync(0xFFFFFFFFu, acc[p], jj + 8);
        ag[p] = __shfl_sync(0xFFFFFFFFu, acc[p], jj + 16);
        ao[p] = __shfl_sync(0xFFFFFFFFu, acc[p], jj + 24);
    }
    if (r < 8) {
        const float bi = sbias[r], bf = sbias[8 + r], bg = sbias[16 + r], bo = sbias[24 + r];
        float2 h[4];
        #pragma unroll
        for (int p = 0; p < 4; p++) {
            float2 vi = unpack2(acc[p]), vf = unpack2(af[p]);
            float2 vg = unpack2(ag[p]), vo = unpack2(ao[p]);
            {   // batch 2p
                float I = sigf(vi.x + bi), F = sigf(vf.x + bf);
                float G = tanhf(vg.x + bg), O = sigf(vo.x + bo);
                float cn = F * cst[p].x + I * G;
                cst[p].x = cn; h[p].x = O * tanhf(cn);
            }
            {   // batch 2p+1
                float I = sigf(vi.y + bi), F = sigf(vf.y + bf);
                float G = tanhf(vg.y + bg), O = sigf(vo.y + bo);
                float cn = F * cst[p].y + I * G;
                cst[p].y = cn; h[p].y = O * tanhf(cn);
            }
        }
        float2* d = hdst + (size_t)(ut * 8 + r) * NP + gp + pg * 4;
        ((float4*)d)[0] = make_float4(h[0].x, h[0].y, h[1].x, h[1].y);
        ((float4*)d)[1] = make_float4(h[2].x, h[2].y, h[3].x, h[3].y);
        if (histdst) {
            float2* hd = histdst + (size_t)(ut * 8 + r) * NP + gp + pg * 4;
            ((float4*)hd)[0] = make_float4(h[0].x, h[0].y, h[1].x, h[1].y);
            ((float4*)hd)[1] = make_float4(h[2].x, h[2].y, h[3].x, h[3].y);
        }
    }
}

// ---------------------------------------------------------------------------
// Persistent kernel: 128 CTAs = 4 batch-tiles x 32 unit-tiles.
// Super-step s: L1@t=s, L2@t=s-1, L3@t=s-2, then grid barrier.
// ---------------------------------------------------------------------------
__global__ void __launch_bounds__(NT, 1)
lstm_persistent(const float* __restrict__ W_ih1, const float* __restrict__ W_hh1,
                const float* __restrict__ b_ih1, const float* __restrict__ b_hh1,
                const float* __restrict__ W_ih2, const float* __restrict__ W_hh2,
                const float* __restrict__ b_ih2, const float* __restrict__ b_hh2,
                const float* __restrict__ W_ih3, const float* __restrict__ W_hh3,
                const float* __restrict__ b_ih3, const float* __restrict__ b_hh3)
{
    extern __shared__ __align__(16) unsigned char smem_raw[];
    Smem* sm = (Smem*)smem_raw;

    const int tid = threadIdx.x;
    const int r   = tid & 31;              // row lane: gate g = r>>3, unit jj = r&7
    const int pg  = tid >> 5;              // pair group 0..7 (4 pairs each)
    const int bt  = blockIdx.x & 3;        // batch tile
    const int ut  = blockIdx.x >> 2;       // unit tile (8 hidden units)
    const int gp  = bt * 32;               // global pair base
    const int grow = ((r >> 3) << 8) + (ut << 3) + (r & 7);  // global gate row

    // ---- stage weights (once, reused 512 steps) ----
    const float* wsrc[5] = { W_hh1, W_ih2, W_hh2, W_ih3, W_hh3 };
    #pragma unroll
    for (int m = 0; m < 5; m++) {
        const float* src = wsrc[m] + (size_t)grow * HD;
        for (int k = tid >> 5; k < HD; k += 8)
            sm->w[m][k * 32 + r] = src[k];
    }
    if (tid < 32) {
        sm->w1ih[r]    = W_ih1[grow];
        sm->bias[0][r] = b_ih1[grow] + b_hh1[grow];
        sm->bias[1][r] = b_ih2[grow] + b_hh2[grow];
        sm->bias[2][r] = b_ih3[grow] + b_hh3[grow];
    }
    __syncthreads();

    // register-resident cell state
    float2 c1[4], c2[4], c3[4];
    #pragma unroll
    for (int p = 0; p < 4; p++) {
        c1[p] = make_float2(0.f, 0.f);
        c2[p] = make_float2(0.f, 0.f);
        c3[p] = make_float2(0.f, 0.f);
    }

    for (int s = 0; s < TT + 2; s++) {
        const int rp = (s + 1) & 1;        // read parity ( = (s-1)&1 )
        const int wp = s & 1;              // write parity

        // ---- layer 1 @ t = s ----
        if (s < TT) {
            unsigned long long acc[4] = {0ull, 0ull, 0ull, 0ull};
            unsigned long long ws1 = splat2(sm->w1ih[r]);
            const ulonglong2* xp = (const ulonglong2*)(&g_x[s][gp + pg * 4]);
            ulonglong2 x0 = xp[0], x1 = xp[1];
            FMA2(acc[0], ws1, x0.x); FMA2(acc[1], ws1, x0.y);
            FMA2(acc[2], ws1, x1.x); FMA2(acc[3], ws1, x1.y);
            accum_mat(acc, &g_hpk[0][rp][0][0], sm->w[0], &sm->act[0][0], gp, r, pg, tid);
            pointwise(acc, c1, sm->bias[0], &g_hpk[0][wp][0][0], nullptr, r, pg, gp, ut);
        }
        // ---- layer 2 @ t = s-1 ----
        if (s >= 1 && s <= TT) {
            unsigned long long acc[4] = {0ull, 0ull, 0ull, 0ull};
            accum_mat(acc, &g_hpk[0][rp][0][0], sm->w[1], &sm->act[0][0], gp, r, pg, tid);
            accum_mat(acc, &g_hpk[1][rp][0][0], sm->w[2], &sm->act[0][0], gp, r, pg, tid);
            pointwise(acc, c2, sm->bias[1], &g_hpk[1][wp][0][0], nullptr, r, pg, gp, ut);
        }
        // ---- layer 3 @ t = s-2 (also record hist) ----
        if (s >= 2) {
            unsigned long long acc[4] = {0ull, 0ull, 0ull, 0ull};
            accum_mat(acc, &g_hpk[1][rp][0][0], sm->w[3], &sm->act[0][0], gp, r, pg, tid);
            accum_mat(acc, &g_hpk[2][rp][0][0], sm->w[4], &sm->act[0][0], gp, r, pg, tid);
            pointwise(acc, c3, sm->bias[2], &g_hpk[2][wp][0][0], &g_hist[s - 2][0][0],
                      r, pg, gp, ut);
        }
        grid_sync((unsigned)(s + 1));
    }
}

// ---------------------------------------------------------------------------
// Init: zero h buffers, reset barrier, build packed-transposed input
// ---------------------------------------------------------------------------
__global__ void init_state(const float* __restrict__ input)
{
    const int idx = blockIdx.x * blockDim.x + threadIdx.x;
    const int stride = gridDim.x * blockDim.x;
    if (idx == 0) { g_bar_count = 0; g_bar_gen = 0; }
    float2* hz = &g_hpk[0][0][0][0];
    for (int i = idx; i < 3 * 2 * HD * NP; i += stride)
        hz[i] = make_float2(0.f, 0.f);
    for (int i = idx; i < TT * NP; i += stride) {
        int t = i >> 7, p = i & (NP - 1);
        ((float2*)g_x)[i] = make_float2(input[(size_t)(2 * p) * TT + t],
                                        input[(size_t)(2 * p + 1) * TT + t]);
    }
}

// ---------------------------------------------------------------------------
// Output head: out[b,t] = dot(h3[t,b,:], W_lin) + b_lin
// block = t, thread = b; hist float layout [t][k][b] is coalesced over b.
// ---------------------------------------------------------------------------
__global__ void __launch_bounds__(256)
linear_head(const float* __restrict__ W_lin, const float* __restrict__ b_lin,
            float* __restrict__ out)
{
    __shared__ float sw[HD];
    const int t = blockIdx.x, b = threadIdx.x;
    sw[b] = W_lin[b];
    __syncthreads();
    const float* hp = (const float*)&g_hist[t][0][0];
    float s = 0.f;
    #pragma unroll 8
    for (int k = 0; k < HD; k++)
        s += hp[(size_t)k * BB + b] * sw[k];
    out[(size_t)b * TT + t] = s + b_lin[0];
}

// ---------------------------------------------------------------------------
// 3 graph nodes total: init -> persistent -> head
// ---------------------------------------------------------------------------
extern "C" void kernel_launch(void* const* d_in, const int* in_sizes, int n_in,
                              void* d_out, int out_size)
{
    const float* input = (const float*)d_in[0];
    const float* W_ih1 = (const float*)d_in[1];
    const float* W_hh1 = (const float*)d_in[2];
    const float* b_ih1 = (const float*)d_in[3];
    const float* b_hh1 = (const float*)d_in[4];
    const float* W_ih2 = (const float*)d_in[5];
    const float* W_hh2 = (const float*)d_in[6];
    const float* b_ih2 = (const float*)d_in[7];
    const float* b_hh2 = (const float*)d_in[8];
    const float* W_ih3 = (const float*)d_in[9];
    const float* W_hh3 = (const float*)d_in[10];
    const float* b_ih3 = (const float*)d_in[11];
    const float* b_hh3 = (const float*)d_in[12];
    const float* W_lin = (const float*)d_in[13];
    const float* b_lin = (const float*)d_in[14];
    float* out = (float*)d_out;

    cudaFuncSetAttribute(lstm_persistent,
                         cudaFuncAttributeMaxDynamicSharedMemorySize, (int)SMEM_BYTES);

    init_state<<<256, 256>>>(input);
    lstm_persistent<<<NB, NT, SMEM_BYTES>>>(W_ih1, W_hh1, b_ih1, b_hh1,
                                            W_ih2, W_hh2, b_ih2, b_hh2,
                                            W_ih3, W_hh3, b_ih3, b_hh3);
    linear_head<<<TT, 256>>>(W_lin, b_lin, out);
}

// round 9
// speedup vs baseline: 1.0541x; 1.0002x over previous
#include <cuda_runtime.h>
#include <cuda_bf16.h>
#include <cstdint>

#define HD   256          // hidden dim
#define BB   256          // batch
#define TT   512          // seq len
#define NP   (BB/2)       // batch pairs = 128
#define NB   128          // persistent grid size (1 CTA/SM, co-resident)
#define NT   256          // threads per CTA

// ---------------------------------------------------------------------------
// Global state (allocation-free scratch)
// Packed-pair layout: [k][pair] float2  (pair p = batches 2p, 2p+1)
// ---------------------------------------------------------------------------
__device__ float2 g_hpk[3][2][HD][NP];      // ping-pong h per layer, 3MB
__device__ float2 g_x[TT][NP];              // transposed packed input, 512KB
__device__ float2 g_hist[TT][HD][NP];       // h3 history, 134MB
__device__ int               g_bar_count;
__device__ volatile unsigned g_bar_gen;

// ---------------------------------------------------------------------------
// Packed f32x2 (Blackwell FFMA2 via PTX only)
// ---------------------------------------------------------------------------
#define FMA2(acc, a, b) asm("fma.rn.f32x2 %0, %1, %2, %0;" : "+l"(acc) : "l"(a), "l"(b))
__device__ __forceinline__ unsigned long long splat2(float w) {
    unsigned long long r; asm("mov.b64 %0, {%1, %1};" : "=l"(r) : "f"(w)); return r;
}
__device__ __forceinline__ float2 unpack2(unsigned long long v) {
    float2 r; asm("mov.b64 {%0, %1}, %2;" : "=f"(r.x), "=f"(r.y) : "l"(v)); return r;
}
__device__ __forceinline__ float sigf(float x) { return 1.f / (1.f + __expf(-x)); }

// ---------------------------------------------------------------------------
// SMEM layout (~192.5 KB dynamic)
// ---------------------------------------------------------------------------
struct Smem {
    float  w[5][HD * 32];        // 5 weight slices [k][32 rows], 160KB
    float2 act[2][64 * 32];      // double-buffered act chunk [k_local][32 pairs], 32KB
    float  w1ih[32];             // layer-1 input column
    float  bias[3][32];          // fused b_ih + b_hh per row
};
#define SMEM_BYTES (sizeof(Smem))

// ---------------------------------------------------------------------------
// Grid barrier (sense via monotonically increasing generation)
// ---------------------------------------------------------------------------
__device__ __forceinline__ void grid_sync(unsigned target) {
    __syncthreads();
    if (threadIdx.x == 0) {
        __threadfence();
        if (atomicAdd(&g_bar_count, 1) == NB - 1) {
            g_bar_count = 0;
            __threadfence();
            g_bar_gen = target;
        } else {
            while (g_bar_gen < target) { }
            __threadfence();
        }
    }
    __syncthreads();
}

// ---------------------------------------------------------------------------
// acc[p] += sum_k W[k][r] * act_pair[k][gp + pg*4 + p],  k = 0..255
// 4 chunks of 64 k, double-buffered SMEM staging with LDG.cg prefetch.
// Warp = 32 rows (lane r), all lanes share pair-group pg.
// ---------------------------------------------------------------------------
__device__ __forceinline__ void accum_mat(
    unsigned long long acc[4],
    const float2* __restrict__ gact,   // [256][128] activation slice base
    const float*  __restrict__ sw,     // [256][32] weight slice
    float2* sbuf,                      // [2][64*32]
    int gp, int r, int pg, int tid)
{
    const int kl = tid >> 2;          // 0..63 : k within chunk
    const int q  = tid & 3;           // quarter of the 32-pair row

    // stage chunk 0
    {
        const float4* s0 = (const float4*)(gact + (size_t)kl * NP + gp) + q * 4;
        float4 p0 = __ldcg(s0 + 0), p1 = __ldcg(s0 + 1),
               p2 = __ldcg(s0 + 2), p3 = __ldcg(s0 + 3);
        float4* d0 = (float4*)(sbuf + (size_t)kl * 32) + q * 4;
        d0[0] = p0; d0[1] = p1; d0[2] = p2; d0[3] = p3;
    }
    __syncthreads();

    #pragma unroll
    for (int c = 0; c < 4; c++) {
        float4 n0, n1, n2, n3;
        if (c < 3) {
            const float4* sn = (const float4*)(gact + ((size_t)(c + 1) * 64 + kl) * NP + gp) + q * 4;
            n0 = __ldcg(sn + 0); n1 = __ldcg(sn + 1);
            n2 = __ldcg(sn + 2); n3 = __ldcg(sn + 3);
        }
        const float2* ab = sbuf + (size_t)(c & 1) * (64 * 32);
        const float*  wk = sw + c * 64 * 32;
        #pragma unroll 8
        for (int k = 0; k < 64; k++) {
            unsigned long long ws = splat2(wk[k * 32 + r]);
            const ulonglong2* ap = (const ulonglong2*)(ab + k * 32 + pg * 4);
            ulonglong2 u0 = ap[0], u1 = ap[1];
            FMA2(acc[0], ws, u0.x);
            FMA2(acc[1], ws, u0.y);
            FMA2(acc[2], ws, u1.x);
            FMA2(acc[3], ws, u1.y);
        }
        if (c < 3) {
            float4* dn = (float4*)(sbuf + (size_t)((c + 1) & 1) * (64 * 32) + (size_t)kl * 32) + q * 4;
            dn[0] = n0; dn[1] = n1; dn[2] = n2; dn[3] = n3;
            __syncthreads();
        }
    }
}

// ---------------------------------------------------------------------------
// LSTM pointwise: gather 4 gates via warp shuffle (row r = g*8+jj), update
// register-resident c, write h pairs to global (and optionally hist).
// ---------------------------------------------------------------------------
__device__ __forceinline__ void pointwise(
    unsigned long long acc[4], float2 cst[4],
    const float* sbias, float2* hdst, float2* histdst,
    int r, int pg, int gp, int ut)
{
    const int jj = r & 7;
    unsigned long long af[4], ag[4], ao[4];
    #pragma unroll
    for (int p = 0; p < 4; p++) {
        af[p] = __shfl_sync(0xFFFFFFFFu, acc[p], jj + 8);
        ag[p] = __shfl_sync(0xFFFFFFFFu, acc[p], jj + 16);
        ao[p] = __shfl_sync(0xFFFFFFFFu, acc[p], jj + 24);
    }
    if (r < 8) {
        const float bi = sbias[r], bf = sbias[8 + r], bg = sbias[16 + r], bo = sbias[24 + r];
        float2 h[4];
        #pragma unroll
        for (int p = 0; p < 4; p++) {
            float2 vi = unpack2(acc[p]), vf = unpack2(af[p]);
            float2 vg = unpack2(ag[p]), vo = unpack2(ao[p]);
            {   // batch 2p
                float I = sigf(vi.x + bi), F = sigf(vf.x + bf);
                float G = tanhf(vg.x + bg), O = sigf(vo.x + bo);
                float cn = F * cst[p].x + I * G;
                cst[p].x = cn; h[p].x = O * tanhf(cn);
            }
            {   // batch 2p+1
                float I = sigf(vi.y + bi), F = sigf(vf.y + bf);
                float G = tanhf(vg.y + bg), O = sigf(vo.y + bo);
                float cn = F * cst[p].y + I * G;
                cst[p].y = cn; h[p].y = O * tanhf(cn);
            }
        }
        float2* d = hdst + (size_t)(ut * 8 + r) * NP + gp + pg * 4;
        ((float4*)d)[0] = make_float4(h[0].x, h[0].y, h[1].x, h[1].y);
        ((float4*)d)[1] = make_float4(h[2].x, h[2].y, h[3].x, h[3].y);
        if (histdst) {
            float2* hd = histdst + (size_t)(ut * 8 + r) * NP + gp + pg * 4;
            ((float4*)hd)[0] = make_float4(h[0].x, h[0].y, h[1].x, h[1].y);
            ((float4*)hd)[1] = make_float4(h[2].x, h[2].y, h[3].x, h[3].y);
        }
    }
}

// ---------------------------------------------------------------------------
// Persistent kernel: 128 CTAs = 4 batch-tiles x 32 unit-tiles.
// Super-step s: L1@t=s, L2@t=s-1, L3@t=s-2, then grid barrier.
// ---------------------------------------------------------------------------
__global__ void __launch_bounds__(NT, 1)
lstm_persistent(const float* __restrict__ W_ih1, const float* __restrict__ W_hh1,
                const float* __restrict__ b_ih1, const float* __restrict__ b_hh1,
                const float* __restrict__ W_ih2, const float* __restrict__ W_hh2,
                const float* __restrict__ b_ih2, const float* __restrict__ b_hh2,
                const float* __restrict__ W_ih3, const float* __restrict__ W_hh3,
                const float* __restrict__ b_ih3, const float* __restrict__ b_hh3)
{
    extern __shared__ __align__(16) unsigned char smem_raw[];
    Smem* sm = (Smem*)smem_raw;

    const int tid = threadIdx.x;
    const int r   = tid & 31;              // row lane: gate g = r>>3, unit jj = r&7
    const int pg  = tid >> 5;              // pair group 0..7 (4 pairs each)
    const int bt  = blockIdx.x & 3;        // batch tile
    const int ut  = blockIdx.x >> 2;       // unit tile (8 hidden units)
    const int gp  = bt * 32;               // global pair base
    const int grow = ((r >> 3) << 8) + (ut << 3) + (r & 7);  // global gate row

    // ---- stage weights (once, reused 512 steps) ----
    const float* wsrc[5] = { W_hh1, W_ih2, W_hh2, W_ih3, W_hh3 };
    #pragma unroll
    for (int m = 0; m < 5; m++) {
        const float* src = wsrc[m] + (size_t)grow * HD;
        for (int k = tid >> 5; k < HD; k += 8)
            sm->w[m][k * 32 + r] = src[k];
    }
    if (tid < 32) {
        sm->w1ih[r]    = W_ih1[grow];
        sm->bias[0][r] = b_ih1[grow] + b_hh1[grow];
        sm->bias[1][r] = b_ih2[grow] + b_hh2[grow];
        sm->bias[2][r] = b_ih3[grow] + b_hh3[grow];
    }
    __syncthreads();

    // register-resident cell state
    float2 c1[4], c2[4], c3[4];
    #pragma unroll
    for (int p = 0; p < 4; p++) {
        c1[p] = make_float2(0.f, 0.f);
        c2[p] = make_float2(0.f, 0.f);
        c3[p] = make_float2(0.f, 0.f);
    }

    for (int s = 0; s < TT + 2; s++) {
        const int rp = (s + 1) & 1;        // read parity ( = (s-1)&1 )
        const int wp = s & 1;              // write parity

        // ---- layer 1 @ t = s ----
        if (s < TT) {
            unsigned long long acc[4] = {0ull, 0ull, 0ull, 0ull};
            unsigned long long ws1 = splat2(sm->w1ih[r]);
            const ulonglong2* xp = (const ulonglong2*)(&g_x[s][gp + pg * 4]);
            ulonglong2 x0 = xp[0], x1 = xp[1];
            FMA2(acc[0], ws1, x0.x); FMA2(acc[1], ws1, x0.y);
            FMA2(acc[2], ws1, x1.x); FMA2(acc[3], ws1, x1.y);
            accum_mat(acc, &g_hpk[0][rp][0][0], sm->w[0], &sm->act[0][0], gp, r, pg, tid);
            pointwise(acc, c1, sm->bias[0], &g_hpk[0][wp][0][0], nullptr, r, pg, gp, ut);
        }
        // ---- layer 2 @ t = s-1 ----
        if (s >= 1 && s <= TT) {
            unsigned long long acc[4] = {0ull, 0ull, 0ull, 0ull};
            accum_mat(acc, &g_hpk[0][rp][0][0], sm->w[1], &sm->act[0][0], gp, r, pg, tid);
            accum_mat(acc, &g_hpk[1][rp][0][0], sm->w[2], &sm->act[0][0], gp, r, pg, tid);
            pointwise(acc, c2, sm->bias[1], &g_hpk[1][wp][0][0], nullptr, r, pg, gp, ut);
        }
        // ---- layer 3 @ t = s-2 (also record hist) ----
        if (s >= 2) {
            unsigned long long acc[4] = {0ull, 0ull, 0ull, 0ull};
            accum_mat(acc, &g_hpk[1][rp][0][0], sm->w[3], &sm->act[0][0], gp, r, pg, tid);
            accum_mat(acc, &g_hpk[2][rp][0][0], sm->w[4], &sm->act[0][0], gp, r, pg, tid);
            pointwise(acc, c3, sm->bias[2], &g_hpk[2][wp][0][0], &g_hist[s - 2][0][0],
                      r, pg, gp, ut);
        }
        grid_sync((unsigned)(s + 1));
    }
}

// ---------------------------------------------------------------------------
// Init: zero h buffers, reset barrier, build packed-transposed input
// ---------------------------------------------------------------------------
__global__ void init_state(const float* __restrict__ input)
{
    const int idx = blockIdx.x * blockDim.x + threadIdx.x;
    const int stride = gridDim.x * blockDim.x;
    if (idx == 0) { g_bar_count = 0; g_bar_gen = 0; }
    float2* hz = &g_hpk[0][0][0][0];
    for (int i = idx; i < 3 * 2 * HD * NP; i += stride)
        hz[i] = make_float2(0.f, 0.f);
    for (int i = idx; i < TT * NP; i += stride) {
        int t = i >> 7, p = i & (NP - 1);
        ((float2*)g_x)[i] = make_float2(input[(size_t)(2 * p) * TT + t],
                                        input[(size_t)(2 * p + 1) * TT + t]);
    }
}

// ---------------------------------------------------------------------------
// Output head: out[b,t] = dot(h3[t,b,:], W_lin) + b_lin
// block = t, thread = b; hist float layout [t][k][b] is coalesced over b.
// ---------------------------------------------------------------------------
__global__ void __launch_bounds__(256)
linear_head(const float* __restrict__ W_lin, const float* __restrict__ b_lin,
            float* __restrict__ out)
{
    __shared__ float sw[HD];
    const int t = blockIdx.x, b = threadIdx.x;
    sw[b] = W_lin[b];
    __syncthreads();
    const float* hp = (const float*)&g_hist[t][0][0];
    float s = 0.f;
    #pragma unroll 8
    for (int k = 0; k < HD; k++)
        s += hp[(size_t)k * BB + b] * sw[k];
    out[(size_t)b * TT + t] = s + b_lin[0];
}

// ---------------------------------------------------------------------------
// 3 graph nodes total: init -> persistent -> head
// ---------------------------------------------------------------------------
extern "C" void kernel_launch(void* const* d_in, const int* in_sizes, int n_in,
                              void* d_out, int out_size)
{
    const float* input = (const float*)d_in[0];
    const float* W_ih1 = (const float*)d_in[1];
    const float* W_hh1 = (const float*)d_in[2];
    const float* b_ih1 = (const float*)d_in[3];
    const float* b_hh1 = (const float*)d_in[4];
    const float* W_ih2 = (const float*)d_in[5];
    const float* W_hh2 = (const float*)d_in[6];
    const float* b_ih2 = (const float*)d_in[7];
    const float* b_hh2 = (const float*)d_in[8];
    const float* W_ih3 = (const float*)d_in[9];
    const float* W_hh3 = (const float*)d_in[10];
    const float* b_ih3 = (const float*)d_in[11];
    const float* b_hh3 = (const float*)d_in[12];
    const float* W_lin = (const float*)d_in[13];
    const float* b_lin = (const float*)d_in[14];
    float* out = (float*)d_out;

    cudaFuncSetAttribute(lstm_persistent,
                         cudaFuncAttributeMaxDynamicSharedMemorySize, (int)SMEM_BYTES);

    init_state<<<256, 256>>>(input);
    lstm_persistent<<<NB, NT, SMEM_BYTES>>>(W_ih1, W_hh1, b_ih1, b_hh1,
                                            W_ih2, W_hh2, b_ih2, b_hh2,
                                            W_ih3, W_hh3, b_ih3, b_hh3);
    linear_head<<<TT, 256>>>(W_lin, b_lin, out);
}